// round 1
// baseline (speedup 1.0000x reference)
#include <cuda_runtime.h>
#include <math.h>

// Fixed problem shapes
#define HH 128
#define WW 128
#define NPIX 16384          // H*W
#define CDIM 128
#define NB 2
#define NV 6
#define BVI 12              // B*V

// ---------------- scratch (device globals; no allocs) ----------------
__device__ float g_bufA[(size_t)BVI * CDIM * NPIX];   // merge1 out -> g1 (fwd GRU out)
__device__ float g_bufB[(size_t)BVI * CDIM * NPIX];   // dw out -> g2 (bwd GRU out)
__device__ float g_bufC[(size_t)BVI * CDIM * NPIX];   // merged f (residual applied)
__device__ float g_hg  [(size_t)BVI * 2 * CDIM * NPIX]; // GRU linear output (hidden|gate)
__device__ float g_alp [(size_t)BVI * NPIX];
__device__ float g_pool[(size_t)NB * CDIM * NPIX];
__device__ float g_u   [(size_t)NB * CDIM * NPIX];

__device__ __forceinline__ float gelu_exact(float x) {
    return 0.5f * x * (1.0f + erff(x * 0.70710678118654752f));
}

// ---------------- generic 1x1-conv GEMM: Out[m,p] = W[m,:]@X[:,p] ----------------
// X layout: per-image channel-major: X[img][k][pix], pix contiguous.
// EPI: 0 = (+bias if given); 1 = gelu(+bias); 2 = +bias + residual (Res, CDIM channels)
constexpr int BM = 128, BN = 128, BK = 8, TM = 8, TN = 8;

template <int KTOT, int MTOT, int EPI, bool SPLIT>
__global__ __launch_bounds__(256) void gemm1x1(
    const float* __restrict__ X0, const float* __restrict__ X1,
    const float* __restrict__ W,  const float* __restrict__ Bias,
    const float* __restrict__ Res, float* __restrict__ Out)
{
    __shared__ float As[BK][BM];
    __shared__ float Bs[BK][BN];

    const int img = blockIdx.z;
    const int p0  = blockIdx.x * BN;
    const int m0  = blockIdx.y * BM;
    const int tid = threadIdx.x;
    const int tx  = tid & 15;
    const int ty  = tid >> 4;

    float acc[TM][TN];
#pragma unroll
    for (int i = 0; i < TM; i++)
#pragma unroll
        for (int j = 0; j < TN; j++) acc[i][j] = 0.f;

    for (int k0 = 0; k0 < KTOT; k0 += BK) {
        // A tile: W[m0..m0+127][k0..k0+7]  (stored transposed As[k][m])
#pragma unroll
        for (int l = 0; l < 4; l++) {
            int i = tid + l * 256;
            int m = i >> 3, k = i & 7;
            As[k][m] = W[(size_t)(m0 + m) * KTOT + k0 + k];
        }
        // B tile: X[k0..k0+7][p0..p0+127]
#pragma unroll
        for (int l = 0; l < 4; l++) {
            int i = tid + l * 256;
            int k = i >> 7, n = i & 127;
            int kk = k0 + k;
            float v;
            if (SPLIT) {
                if (kk < CDIM) v = X0[((size_t)img * CDIM + kk) * NPIX + p0 + n];
                else           v = X1[((size_t)img * CDIM + (kk - CDIM)) * NPIX + p0 + n];
            } else {
                v = X0[((size_t)img * KTOT + kk) * NPIX + p0 + n];
            }
            Bs[k][n] = v;
        }
        __syncthreads();

#pragma unroll
        for (int k = 0; k < BK; k++) {
            float a[TM], b[TN];
            float4 t;
            t = *reinterpret_cast<const float4*>(&As[k][ty * TM]);     a[0]=t.x;a[1]=t.y;a[2]=t.z;a[3]=t.w;
            t = *reinterpret_cast<const float4*>(&As[k][ty * TM + 4]); a[4]=t.x;a[5]=t.y;a[6]=t.z;a[7]=t.w;
            t = *reinterpret_cast<const float4*>(&Bs[k][tx * TN]);     b[0]=t.x;b[1]=t.y;b[2]=t.z;b[3]=t.w;
            t = *reinterpret_cast<const float4*>(&Bs[k][tx * TN + 4]); b[4]=t.x;b[5]=t.y;b[6]=t.z;b[7]=t.w;
#pragma unroll
            for (int i = 0; i < TM; i++)
#pragma unroll
                for (int j = 0; j < TN; j++)
                    acc[i][j] = fmaf(a[i], b[j], acc[i][j]);
        }
        __syncthreads();
    }

#pragma unroll
    for (int i = 0; i < TM; i++) {
        int m = m0 + ty * TM + i;
        float bias = Bias ? Bias[m] : 0.f;
        size_t obase = ((size_t)img * MTOT + m) * NPIX + p0 + tx * TN;
#pragma unroll
        for (int j = 0; j < TN; j++) {
            float v = acc[i][j] + bias;
            if (EPI == 1) v = gelu_exact(v);
            if (EPI == 2) v += Res[((size_t)img * CDIM + m) * NPIX + p0 + tx * TN + j];
            acc[i][j] = v;
        }
        *reinterpret_cast<float4*>(&Out[obase])     = make_float4(acc[i][0], acc[i][1], acc[i][2], acc[i][3]);
        *reinterpret_cast<float4*>(&Out[obase + 4]) = make_float4(acc[i][4], acc[i][5], acc[i][6], acc[i][7]);
    }
}

// ---------------- depthwise 3x3 + bias + GELU ----------------
__global__ __launch_bounds__(256) void dw3x3(
    const float* __restrict__ in, const float* __restrict__ wd,
    const float* __restrict__ bd, float* __restrict__ out)
{
    int c = blockIdx.y, img = blockIdx.z;
    int pix = blockIdx.x * 256 + threadIdx.x;
    int h = pix >> 7, w = pix & 127;
    const float* p = in + ((size_t)img * CDIM + c) * NPIX;
    float s = bd[c];
#pragma unroll
    for (int ky = 0; ky < 3; ky++) {
        int hh = h + ky - 1;
        if ((unsigned)hh >= 128u) continue;
#pragma unroll
        for (int kx = 0; kx < 3; kx++) {
            int ww = w + kx - 1;
            if ((unsigned)ww >= 128u) continue;
            s = fmaf(wd[c * 9 + ky * 3 + kx], p[hh * WW + ww], s);
        }
    }
    out[((size_t)img * CDIM + c) * NPIX + pix] = gelu_exact(s);
}

// ---------------- minGRU scan over V (forward; both passes are forward: the H-flips cancel) ----------------
__global__ __launch_bounds__(256) void gru_scan(const float* __restrict__ hg, float* __restrict__ g)
{
    int c = blockIdx.y, b = blockIdx.z;
    int pix = blockIdx.x * 256 + threadIdx.x;
    float h = 0.f;
#pragma unroll
    for (int v = 0; v < NV; v++) {
        size_t base = (((size_t)(b * NV + v)) * 2 * CDIM + c) * NPIX + pix;
        float hid = hg[base];
        float gt  = hg[base + (size_t)CDIM * NPIX];
        float z  = 1.f / (1.f + expf(-gt));
        float ht = (hid >= 0.f) ? (hid + 0.5f) : (1.f / (1.f + expf(-hid)));
        h = (1.f - z) * h + z * ht;
        g[(((size_t)(b * NV + v)) * CDIM + c) * NPIX + pix] = h;
    }
}

// ---------------- alpha: 3x3 conv C->1 ----------------
__global__ __launch_bounds__(256) void alpha_conv(
    const float* __restrict__ g2, const float* __restrict__ aw,
    const float* __restrict__ ab, float* __restrict__ alpha)
{
    __shared__ float w[1152];
    for (int i = threadIdx.x; i < 1152; i += 256) w[i] = aw[i];
    __syncthreads();
    int img = blockIdx.z;
    int pix = blockIdx.x * 256 + threadIdx.x;
    int h = pix >> 7, x = pix & 127;
    float s = ab[0];
    const float* base = g2 + (size_t)img * CDIM * NPIX;
    for (int c = 0; c < CDIM; c++) {
        const float* p  = base + (size_t)c * NPIX;
        const float* wc = w + c * 9;
#pragma unroll
        for (int ky = 0; ky < 3; ky++) {
            int hh = h + ky - 1;
            if ((unsigned)hh >= 128u) continue;
#pragma unroll
            for (int kx = 0; kx < 3; kx++) {
                int ww = x + kx - 1;
                if ((unsigned)ww >= 128u) continue;
                s = fmaf(wc[ky * 3 + kx], p[hh * WW + ww], s);
            }
        }
    }
    alpha[(size_t)img * NPIX + pix] = s;
}

// ---------------- softmax over V + weighted pool ----------------
__global__ __launch_bounds__(256) void pool_k(
    const float* __restrict__ g2, const float* __restrict__ alpha, float* __restrict__ out)
{
    int b = blockIdx.z;
    int pix = blockIdx.x * 256 + threadIdx.x;
    float a[NV];
    float mx = -1e30f;
#pragma unroll
    for (int v = 0; v < NV; v++) {
        a[v] = alpha[(size_t)(b * NV + v) * NPIX + pix];
        mx = fmaxf(mx, a[v]);
    }
    float sum = 0.f;
#pragma unroll
    for (int v = 0; v < NV; v++) { a[v] = expf(a[v] - mx); sum += a[v]; }
    float inv = 1.f / sum;
#pragma unroll
    for (int v = 0; v < NV; v++) a[v] *= inv;
    for (int c = 0; c < CDIM; c++) {
        float s = 0.f;
#pragma unroll
        for (int v = 0; v < NV; v++)
            s = fmaf(a[v], g2[(((size_t)(b * NV + v)) * CDIM + c) * NPIX + pix], s);
        out[((size_t)b * CDIM + c) * NPIX + pix] = s;
    }
}

// ---------------- pixel-shuffle(4) + 3x3 conv 8->3 (resize 512->512 is identity) ----------------
__global__ __launch_bounds__(256) void outc_k(
    const float* __restrict__ u, const float* __restrict__ wt,
    const float* __restrict__ bs, float* __restrict__ out)
{
    __shared__ float w[216];
    if (threadIdx.x < 216) w[threadIdx.x] = wt[threadIdx.x];
    __syncthreads();
    int b = blockIdx.z, co = blockIdx.y;
    int idx = blockIdx.x * 256 + threadIdx.x;       // pixel in 512x512
    int y = idx >> 9, x = idx & 511;
    float s = bs[co];
    const float* ub = u + (size_t)b * CDIM * NPIX;
#pragma unroll
    for (int ky = 0; ky < 3; ky++) {
        int yy = y + ky - 1;
        if ((unsigned)yy >= 512u) continue;
        int sy = yy & 3, hy = yy >> 2;
#pragma unroll
        for (int kx = 0; kx < 3; kx++) {
            int xx = x + kx - 1;
            if ((unsigned)xx >= 512u) continue;
            int sx = xx & 3, hx = xx >> 2;
            const float* up = ub + (size_t)(sy * 4 + sx) * NPIX + hy * WW + hx;
#pragma unroll
            for (int ci = 0; ci < 8; ci++)
                s = fmaf(w[(co * 8 + ci) * 9 + ky * 3 + kx], up[(size_t)ci * 16 * NPIX], s);
        }
    }
    out[((size_t)b * 3 + co) * (512 * 512) + idx] = s;
}

// ---------------- launch ----------------
extern "C" void kernel_launch(void* const* d_in, const int* in_sizes, int n_in,
                              void* d_out, int out_size)
{
    const float* feats     = (const float*)d_in[0];
    const float* prj       = (const float*)d_in[1];
    const float* merge_w1  = (const float*)d_in[2];
    const float* merge_b1  = (const float*)d_in[3];
    const float* merge_wd  = (const float*)d_in[4];
    const float* merge_bd  = (const float*)d_in[5];
    const float* merge_w2  = (const float*)d_in[6];
    const float* merge_b2  = (const float*)d_in[7];
    const float* gru_w     = (const float*)d_in[8];
    const float* gru_bw    = (const float*)d_in[9];
    const float* alpha_w   = (const float*)d_in[10];
    const float* alpha_b   = (const float*)d_in[11];
    const float* up_w      = (const float*)d_in[12];
    const float* up_b      = (const float*)d_in[13];
    const float* outc_w    = (const float*)d_in[14];
    const float* outc_b    = (const float*)d_in[15];
    // d_in[16], d_in[17] = oh, ow (fixed 512; resize is identity)

    float *bufA, *bufB, *bufC, *hg, *alp, *pool, *u;
    cudaGetSymbolAddress((void**)&bufA, g_bufA);
    cudaGetSymbolAddress((void**)&bufB, g_bufB);
    cudaGetSymbolAddress((void**)&bufC, g_bufC);
    cudaGetSymbolAddress((void**)&hg,   g_hg);
    cudaGetSymbolAddress((void**)&alp,  g_alp);
    cudaGetSymbolAddress((void**)&pool, g_pool);
    cudaGetSymbolAddress((void**)&u,    g_u);

    // merge: 1x1 (2C->C) + GELU
    gemm1x1<256, 128, 1, true ><<<dim3(128, 1, BVI), 256>>>(feats, prj, merge_w1, merge_b1, nullptr, bufA);
    // depthwise 3x3 + GELU
    dw3x3<<<dim3(64, CDIM, BVI), 256>>>(bufA, merge_wd, merge_bd, bufB);
    // 1x1 (C->C) + bias + residual(feats)
    gemm1x1<128, 128, 2, false><<<dim3(128, 1, BVI), 256>>>(bufB, nullptr, merge_w2, merge_b2, feats, bufC);
    // fwd GRU linear (C -> 2C)
    gemm1x1<128, 256, 0, false><<<dim3(128, 2, BVI), 256>>>(bufC, nullptr, gru_w, nullptr, nullptr, hg);
    gru_scan<<<dim3(64, CDIM, NB), 256>>>(hg, bufA);
    // bwd GRU linear (flips along H cancel -> forward scan again)
    gemm1x1<128, 256, 0, false><<<dim3(128, 2, BVI), 256>>>(bufA, nullptr, gru_bw, nullptr, nullptr, hg);
    gru_scan<<<dim3(64, CDIM, NB), 256>>>(hg, bufB);
    // alpha conv + softmax pool over V
    alpha_conv<<<dim3(64, 1, BVI), 256>>>(bufB, alpha_w, alpha_b, alp);
    pool_k<<<dim3(64, 1, NB), 256>>>(bufB, alp, pool);
    // up 1x1 conv
    gemm1x1<128, 128, 0, false><<<dim3(128, 1, NB), 256>>>(pool, nullptr, up_w, up_b, nullptr, u);
    // pixel shuffle + outc 3x3
    outc_k<<<dim3(1024, 3, NB), 256>>>(u, outc_w, outc_b, (float*)d_out);
}